// round 6
// baseline (speedup 1.0000x reference)
#include <cuda_runtime.h>
#include <math.h>
#include <float.h>

// Accurate libdevice math (same routines XLA GPU lowers f32 exp/log to).
extern "C" __device__ float __nv_expf(float);
extern "C" __device__ float __nv_logf(float);

// B=64, T=500 -> 32000 (b,t) rows; NLOGIT=13, TR=5, P=6 pairs.
// pred  : (64,500,13,5,6) f32 -> 390 floats per (b,t)
// target: (64,500,5,5,13) f32 -> 325 floats per (b,t)
// mic_locs: (4,3) f32 ; out: [loss, acc] f32
//
// Layout: 256 threads = 8 warps = 4 rows x 2 warps.
// Warp h of a row owns mic-pairs {3h, 3h+1, 3h+2}; after one block sync the
// two warps of a row are fully independent (halved serial chains per warp).

#define NBT    32000
#define RPB    4             // rows per block
#define NBLK   (NBT / RPB)   // 8000
#define NBUCK  32

__device__ double             g_bl[NBUCK];   // zero-init; last block re-zeroes
__device__ unsigned long long g_bc[NBUCK];
__device__ unsigned long long g_bn[NBUCK];
__device__ unsigned           g_cnt;         // wraps to 0 every full launch

// Lexicographic (itertools) permutation -> packed 4-bit digits.
__device__ __forceinline__ unsigned perm_pack(int p) {
    int avail[5] = {0, 1, 2, 3, 4};
    const int fact[4] = {24, 6, 2, 1};
    unsigned pk = 0;
#pragma unroll
    for (int i = 0; i < 4; i++) {
        int d = p / fact[i];
        p -= d * fact[i];
        pk |= (unsigned)avail[d] << (4 * i);
#pragma unroll
        for (int j = 0; j < 4; j++)
            if (j >= d) avail[j] = avail[j + 1];
    }
    pk |= (unsigned)avail[0] << 16;
    return pk;
}

__global__ __launch_bounds__(256, 6) void tdoa_main(
    const float* __restrict__ pred,
    const float* __restrict__ target,
    const float* __restrict__ mics,
    float* __restrict__ out, int nout)
{
    __shared__ __align__(16) float s_pred[RPB][390];  // cl*30 + track*6 + pair
    __shared__ __align__(16) float s_tgt[RPB][325];   // tr*65 + comp*13 + c
    __shared__ float         s_lm[RPB][150];          // pair*25 + slot*5 + track
    __shared__ unsigned char s_cls[RPB][32];          // slot*6 + pair
    __shared__ unsigned char s_pc[RPB][32];           // pair*5 + track
    __shared__ unsigned      s_perm[128];             // [120..127] = 0
    __shared__ float         s_mics[12];
    __shared__ double        s_wl[8];
    __shared__ int           s_wc[8], s_wn[8];

    const int tid  = threadIdx.x;
    const int warp = tid >> 5;
    const int lane = tid & 31;
    const int row  = warp >> 1;          // 0..3
    const int h    = warp & 1;           // pair-half: pairs 3h..3h+2
    const int bt   = blockIdx.x * RPB + row;
    const int u    = h * 32 + lane;      // 0..63 within row

    // ---- stage inputs (two warps per row cooperate) ----
    {
        const float2* pb2 = (const float2*)(pred + (size_t)bt * 390u); // 390 even -> 8B aligned
        float2* sp2 = (float2*)&s_pred[row][0];
        for (int i = u; i < 195; i += 64) sp2[i] = pb2[i];
        const float* tb = target + (size_t)bt * 325u;
        for (int i = u; i < 325; i += 64) s_tgt[row][i] = tb[i];
    }
    if (tid < 128) s_perm[tid] = (tid < 120) ? perm_pack(tid) : 0u;
    if (tid < 12)  s_mics[tid] = mics[tid];
    __syncthreads();

    // ---- stable first-<=5 active selection (each warp computes its own) ----
    int f0 = lane, f1 = 32 + lane;
    int tr0 = f0 / 13, c0 = f0 - tr0 * 13;
    int tr1 = f1 / 13, c1 = f1 - tr1 * 13;
    unsigned b0 = __ballot_sync(0xffffffffu, s_tgt[row][tr0 * 65 + c0] != 0.0f);
    unsigned b1 = __ballot_sync(0xffffffffu, s_tgt[row][tr1 * 65 + c1] != 0.0f);
    int act64 = (s_tgt[row][4 * 65 + 12] != 0.0f) ? 1 : 0;   // f = 64
    unsigned long long bits = (unsigned long long)b0 |
                              ((unsigned long long)b1 << 32);
    int total = __popcll(bits) + act64;
    const int v = (total < 5) ? total : 5;

    // fsel computed on all lanes (meaningful for lane<5), broadcast via shfl
    int fsel = 0;
    {
        int sl = (lane < 5) ? lane : 0;
        if (sl < v) {
            if (sl < __popcll(bits)) {
                unsigned long long t = bits;
#pragma unroll
                for (int j = 0; j < 4; j++)
                    if (j < sl) t &= t - 1;
                fsel = __ffsll((long long)t) - 1;
            } else {
                fsel = 64;
            }
        }
    }

    // ---- TDOA class per (slot, my 3 pairs): 15 lanes ----
    {
        int s   = lane / 3;              // slot 0..4 (lane<15)
        int prl = lane - s * 3;          // 0..2
        int pair = 3 * h + prl;
        int f = __shfl_sync(0xffffffffu, fsel, (s < 5) ? s : 0);
        if (lane < 15) {
            int cls = 0;
            if (s < v) {
                const int pa[6]  = {0, 0, 0, 1, 1, 2};
                const int pbx[6] = {1, 2, 3, 2, 3, 3};
                int tr = f / 13, c = f - tr * 13;
                float dist = s_tgt[row][tr * 65 + 52 + c];
                float sx = __fmul_rn(s_tgt[row][tr * 65 + 13 + c], dist);
                float sy = __fmul_rn(s_tgt[row][tr * 65 + 26 + c], dist);
                float sz = __fmul_rn(s_tgt[row][tr * 65 + 39 + c], dist);
                int ma = pa[pair], mb = pbx[pair];
                float dxa = __fsub_rn(sx, s_mics[ma * 3 + 0]);
                float dya = __fsub_rn(sy, s_mics[ma * 3 + 1]);
                float dza = __fsub_rn(sz, s_mics[ma * 3 + 2]);
                float dxb = __fsub_rn(sx, s_mics[mb * 3 + 0]);
                float dyb = __fsub_rn(sy, s_mics[mb * 3 + 1]);
                float dzb = __fsub_rn(sz, s_mics[mb * 3 + 2]);
                float qa = __fadd_rn(__fadd_rn(__fmul_rn(dxa, dxa), __fmul_rn(dya, dya)), __fmul_rn(dza, dza));
                float qb = __fadd_rn(__fadd_rn(__fmul_rn(dxb, dxb), __fmul_rn(dyb, dyb)), __fmul_rn(dzb, dzb));
                float tdoa = __fsub_rn(__fsqrt_rn(qa), __fsqrt_rn(qb));
                cls = (int)rintf(__fdiv_rn(__fmul_rn(tdoa, 24000.0f), 343.0f)) + 6;
            }
            s_cls[row][s * 6 + pair] = (unsigned char)cls;
        }
    }
    __syncwarp();

    // ---- log-softmax per (my 3 pairs, track): 15 lanes ----
    if (lane < 15) {
        const int prl   = lane / 5;          // 0..2
        const int pair  = 3 * h + prl;
        const int track = lane - prl * 5;
        const int base  = track * 6 + pair;
        float x[13];
        float mx = -FLT_MAX;
        int   am = 0;
#pragma unroll
        for (int cl = 0; cl < 13; cl++) {
            x[cl] = s_pred[row][cl * 30 + base];
            if (x[cl] > mx) { mx = x[cl]; am = cl; }  // first-occurrence argmax
        }
        // XLA GPU 32-lane column-reduction tree (leaves 13..31 == 0)
        float t0 = __fadd_rn(__nv_expf(__fsub_rn(x[0], mx)), __nv_expf(__fsub_rn(x[8],  mx)));
        float t1 = __fadd_rn(__nv_expf(__fsub_rn(x[1], mx)), __nv_expf(__fsub_rn(x[9],  mx)));
        float t2 = __fadd_rn(__nv_expf(__fsub_rn(x[2], mx)), __nv_expf(__fsub_rn(x[10], mx)));
        float t3 = __fadd_rn(__nv_expf(__fsub_rn(x[3], mx)), __nv_expf(__fsub_rn(x[11], mx)));
        float t4 = __fadd_rn(__nv_expf(__fsub_rn(x[4], mx)), __nv_expf(__fsub_rn(x[12], mx)));
        float u0 = __fadd_rn(t0, t4);
        float u1 = __fadd_rn(t1, __nv_expf(__fsub_rn(x[5], mx)));
        float u2 = __fadd_rn(t2, __nv_expf(__fsub_rn(x[6], mx)));
        float u3 = __fadd_rn(t3, __nv_expf(__fsub_rn(x[7], mx)));
        float sm = __fadd_rn(__fadd_rn(u0, u2), __fadd_rn(u1, u3));
        float lse = __nv_logf(sm);
        s_pc[row][pair * 5 + track] = (unsigned char)am;
#pragma unroll
        for (int k = 0; k < 5; k++) {
            int idx = (k < v) ? (int)s_cls[row][k * 6 + pair] : 0;
            // lse - shifted[idx], shifted[idx] = x[idx] - mx (same bits)
            float xv = s_pred[row][idx * 30 + base];
            s_lm[row][pair * 25 + k * 5 + track] =
                (k < v) ? __fsub_rn(lse, __fsub_rn(xv, mx)) : 0.0f;
        }
    }
    __syncwarp();

    // ---- per-pair 120-perm argmin over my 3 pairs ----
    const unsigned pk0 = s_perm[lane];
    const unsigned pk1 = s_perm[lane + 32];
    const unsigned pk2 = s_perm[lane + 64];
    const unsigned pk3 = s_perm[lane + 96];

    double wloss = 0.0;
    int    wcorr = 0;
#pragma unroll 1
    for (int prl = 0; prl < 3; prl++) {
        const int pair = 3 * h + prl;
        const float* lm = &s_lm[row][pair * 25];
        // Lazy division: cost = div(s0,5) is monotone in s0; divide only on
        // strict raw improvement; divided-tie keeps earlier index (bitwise
        // identical to reference first-occurrence argmin).
        float bs0  = FLT_MAX;
        float bcst = FLT_MAX;
        int   bidx = 1 << 20;
#pragma unroll
        for (int rep = 0; rep < 4; rep++) {
            unsigned pk = (rep == 0) ? pk0 : (rep == 1) ? pk1 : (rep == 2) ? pk2 : pk3;
            int pe = lane + rep * 32;
            if (pe < 120) {
                float a0 = lm[       (pk        & 15)];
                float a1 = lm[ 5 +  ((pk >> 4)  & 15)];
                float a2 = lm[10 +  ((pk >> 8)  & 15)];
                float a3 = lm[15 +  ((pk >> 12) & 15)];
                float a4 = lm[20 +  ((pk >> 16) & 15)];
                // XLA tree: ((a0+a4)+a2)+(a1+a3), then /5
                float s0 = __fadd_rn(__fadd_rn(__fadd_rn(a0, a4), a2),
                                     __fadd_rn(a1, a3));
                if (s0 < bs0) {
                    float cst = __fdiv_rn(s0, 5.0f);
                    if (cst < bcst) { bcst = cst; bidx = pe; }
                    bs0 = s0;
                }
            }
        }
#pragma unroll
        for (int off = 16; off; off >>= 1) {
            float ov = __shfl_down_sync(0xffffffffu, bcst, off);
            int   oi = __shfl_down_sync(0xffffffffu, bidx, off);
            if (ov < bcst || (ov == bcst && oi < bidx)) { bcst = ov; bidx = oi; }
        }
        if (lane == 0) {
            unsigned pk = s_perm[bidx];
#pragma unroll
            for (int i = 0; i < 5; i++) {
                int s = (pk >> (4 * i)) & 15;   // tgt_perm[i] = tgt[perm[i]]
                if (s < v && (int)s_pc[row][pair * 5 + i] == (int)s_cls[row][s * 6 + pair]) wcorr++;
            }
            wloss += (double)bcst;
        }
    }

    if (lane == 0) {
        s_wl[warp] = wloss;
        s_wc[warp] = wcorr;
        s_wn[warp] = 3 * v;     // two warps/row sum to 6*v
    }
    __syncthreads();

    // ---- block accumulate -> buckets; last block finalizes output ----
    if (tid == 0) {
        double L = 0.0;
        int    C = 0, NP = 0;
#pragma unroll
        for (int i = 0; i < 8; i++) { L += s_wl[i]; C += s_wc[i]; NP += s_wn[i]; }
        int bk = blockIdx.x & (NBUCK - 1);
        atomicAdd(&g_bl[bk], L);
        atomicAdd(&g_bc[bk], (unsigned long long)C);
        atomicAdd(&g_bn[bk], (unsigned long long)NP);
        __threadfence();
    }
    if (warp == 0) {
        unsigned t = 0;
        if (lane == 0) t = atomicInc(&g_cnt, NBLK - 1);  // wraps -> clean state
        t = __shfl_sync(0xffffffffu, t, 0);
        if (t == NBLK - 1) {
            // last block: all producers' fences precede their atomicInc
            double             L = g_bl[lane];
            unsigned long long C = g_bc[lane];
            unsigned long long N = g_bn[lane];
            g_bl[lane] = 0.0;    // re-zero for next replay
            g_bc[lane] = 0ull;
            g_bn[lane] = 0ull;
#pragma unroll
            for (int off = 16; off; off >>= 1) {
                L += __shfl_down_sync(0xffffffffu, L, off);
                C += __shfl_down_sync(0xffffffffu, C, off);
                N += __shfl_down_sync(0xffffffffu, N, off);
            }
            if (lane == 0) {
                if (nout >= 1) out[0] = (float)(L / 192000.0);
                if (nout >= 2) out[1] = (N > 0) ? (float)((double)C / (double)N) : 0.0f;
            }
        }
    }
}

extern "C" void kernel_launch(void* const* d_in, const int* in_sizes, int n_in,
                              void* d_out, int out_size) {
    const float* pred   = (const float*)d_in[0];
    const float* target = (const float*)d_in[1];
    const float* mics   = (const float*)d_in[2];
    (void)in_sizes; (void)n_in;

    tdoa_main<<<NBLK, 256>>>(pred, target, mics, (float*)d_out, out_size);
}

// round 7
// speedup vs baseline: 1.2350x; 1.2350x over previous
#include <cuda_runtime.h>
#include <math.h>
#include <float.h>

// Accurate libdevice math (same routines XLA GPU lowers f32 exp/log to).
extern "C" __device__ float __nv_expf(float);
extern "C" __device__ float __nv_logf(float);

// B=64, T=500 -> 32000 (b,t) rows; NLOGIT=13, TR=5, P=6 pairs.
// pred  : (64,500,13,5,6) f32 -> 390 floats per (b,t)
// target: (64,500,5,5,13) f32 -> 325 floats per (b,t)
// mic_locs: (4,3) f32 ; out: [loss, acc] f32
//
// Layout: 256 threads = 8 warps, one (b,t) row per warp.
// Perm-argmin stage: lanes split into 6 groups of 5; group g owns mic-pair g.

#define NBT    32000
#define WPB    8
#define NBLK   (NBT / WPB)   // 4000
#define NBUCK  32

__device__ double             g_bl[NBUCK];   // zero-init; last block re-zeroes
__device__ unsigned long long g_bc[NBUCK];
__device__ unsigned long long g_bn[NBUCK];
__device__ unsigned           g_cnt;         // wraps to 0 every full launch

// Lexicographic (itertools) permutation -> packed 4-bit digits.
__device__ __forceinline__ unsigned perm_pack(int p) {
    int avail[5] = {0, 1, 2, 3, 4};
    const int fact[4] = {24, 6, 2, 1};
    unsigned pk = 0;
#pragma unroll
    for (int i = 0; i < 4; i++) {
        int d = p / fact[i];
        p -= d * fact[i];
        pk |= (unsigned)avail[d] << (4 * i);
#pragma unroll
        for (int j = 0; j < 4; j++)
            if (j >= d) avail[j] = avail[j + 1];
    }
    pk |= (unsigned)avail[0] << 16;
    return pk;
}

__global__ __launch_bounds__(256, 6) void tdoa_main(
    const float* __restrict__ pred,
    const float* __restrict__ target,
    const float* __restrict__ mics,
    float* __restrict__ out, int nout)
{
    __shared__ __align__(16) float s_pred[WPB][390];  // cl*30 + track*6 + pair
    // s_tgt (325 f) and s_lm (150 f) have disjoint lifetimes -> overlay.
    __shared__ __align__(16) float s_u[WPB][325];
    __shared__ unsigned char s_cls[WPB][32];   // slot*6 + pair
    __shared__ unsigned char s_pc[WPB][32];    // pair*5 + track
    __shared__ unsigned s_perm[128];           // 4-bit digit pack; [120..]=0
    __shared__ unsigned s_eperm[128];          // 5-bit (5k+digit) pack
    __shared__ float    s_mics[12];
    __shared__ float    s_gl[WPB][6];          // per-group best cost
    __shared__ int      s_gc[WPB][6];          // per-group correct count
    __shared__ double   s_wl[WPB];
    __shared__ int      s_wc[WPB], s_wn[WPB];

    const int tid  = threadIdx.x;
    const int w    = tid >> 5;
    const int lane = tid & 31;
    const int bt   = blockIdx.x * WPB + w;

    float* s_tgt = s_u[w];   // phase 1
    float* s_lm  = s_u[w];   // phase 2 (pair*25 + slot*5 + track)

    // ---- stage inputs + block tables ----
    {
        const float2* pb2 = (const float2*)(pred + (size_t)bt * 390u); // even -> 8B aligned
        float2* sp2 = (float2*)&s_pred[w][0];
#pragma unroll
        for (int i = 0; i < 6; i++) sp2[lane + 32 * i] = pb2[lane + 32 * i];
        if (lane < 3) sp2[192 + lane] = pb2[192 + lane];
        const float* tb = target + (size_t)bt * 325u;
        for (int i = lane; i < 325; i += 32) s_tgt[i] = tb[i];
    }
    if (tid < 128) {
        unsigned pk = (tid < 120) ? perm_pack(tid) : 0u;
        s_perm[tid] = pk;
        unsigned ep = 0;
#pragma unroll
        for (int k = 0; k < 5; k++)
            ep |= (unsigned)(5 * k + ((pk >> (4 * k)) & 15)) << (5 * k);
        s_eperm[tid] = ep;
    }
    if (tid < 12) s_mics[tid] = mics[tid];
    __syncthreads();

    // ---- stable first-<=5 active selection via ballots (f = tr*13 + c) ----
    int f0 = lane, f1 = 32 + lane;
    int tr0 = f0 / 13, c0 = f0 - tr0 * 13;
    int tr1 = f1 / 13, c1 = f1 - tr1 * 13;
    unsigned b0 = __ballot_sync(0xffffffffu, s_tgt[tr0 * 65 + c0] != 0.0f);
    unsigned b1 = __ballot_sync(0xffffffffu, s_tgt[tr1 * 65 + c1] != 0.0f);
    int act64 = (s_tgt[4 * 65 + 12] != 0.0f) ? 1 : 0;   // f = 64
    unsigned long long bits = (unsigned long long)b0 |
                              ((unsigned long long)b1 << 32);
    int total = __popcll(bits) + act64;
    const int v = (total < 5) ? total : 5;

    // fsel on lanes 0..4 (others compute lane-0 copy), broadcast by shfl later
    int fsel = 0;
    {
        int sl = (lane < 5) ? lane : 0;
        if (sl < v) {
            if (sl < __popcll(bits)) {
                unsigned long long t = bits;
#pragma unroll
                for (int j = 0; j < 4; j++)
                    if (j < sl) t &= t - 1;
                fsel = __ffsll((long long)t) - 1;
            } else {
                fsel = 64;
            }
        }
    }

    // ---- TDOA class per (slot, pair): 30 lanes ----
    {
        int s  = lane / 6;               // slot (lane<30)
        int pr = lane - s * 6;           // pair
        int f  = __shfl_sync(0xffffffffu, fsel, (s < 5) ? s : 0);
        if (lane < 30) {
            int cls = 0;
            if (s < v) {
                const int pa[6]  = {0, 0, 0, 1, 1, 2};
                const int pbx[6] = {1, 2, 3, 2, 3, 3};
                int tr = f / 13, c = f - tr * 13;
                float dist = s_tgt[tr * 65 + 52 + c];
                float sx = __fmul_rn(s_tgt[tr * 65 + 13 + c], dist);
                float sy = __fmul_rn(s_tgt[tr * 65 + 26 + c], dist);
                float sz = __fmul_rn(s_tgt[tr * 65 + 39 + c], dist);
                int ma = pa[pr], mb = pbx[pr];
                float dxa = __fsub_rn(sx, s_mics[ma * 3 + 0]);
                float dya = __fsub_rn(sy, s_mics[ma * 3 + 1]);
                float dza = __fsub_rn(sz, s_mics[ma * 3 + 2]);
                float dxb = __fsub_rn(sx, s_mics[mb * 3 + 0]);
                float dyb = __fsub_rn(sy, s_mics[mb * 3 + 1]);
                float dzb = __fsub_rn(sz, s_mics[mb * 3 + 2]);
                float qa = __fadd_rn(__fadd_rn(__fmul_rn(dxa, dxa), __fmul_rn(dya, dya)), __fmul_rn(dza, dza));
                float qb = __fadd_rn(__fadd_rn(__fmul_rn(dxb, dxb), __fmul_rn(dyb, dyb)), __fmul_rn(dzb, dzb));
                float tdoa = __fsub_rn(__fsqrt_rn(qa), __fsqrt_rn(qb));
                cls = (int)rintf(__fdiv_rn(__fmul_rn(tdoa, 24000.0f), 343.0f)) + 6;
            }
            s_cls[w][s * 6 + pr] = (unsigned char)cls;
        }
    }
    __syncwarp();

    // ---- log-softmax per (pair, track): 30 lanes ----
    if (lane < 30) {
        const int pair  = lane / 5;
        const int track = lane - pair * 5;
        const int base  = track * 6 + pair;
        float x[13];
        float mx = -FLT_MAX;
        int   am = 0;
#pragma unroll
        for (int cl = 0; cl < 13; cl++) {
            x[cl] = s_pred[w][cl * 30 + base];
            if (x[cl] > mx) { mx = x[cl]; am = cl; }  // first-occurrence argmax
        }
        // XLA GPU 32-lane column-reduction tree (leaves 13..31 == 0)
        float t0 = __fadd_rn(__nv_expf(__fsub_rn(x[0], mx)), __nv_expf(__fsub_rn(x[8],  mx)));
        float t1 = __fadd_rn(__nv_expf(__fsub_rn(x[1], mx)), __nv_expf(__fsub_rn(x[9],  mx)));
        float t2 = __fadd_rn(__nv_expf(__fsub_rn(x[2], mx)), __nv_expf(__fsub_rn(x[10], mx)));
        float t3 = __fadd_rn(__nv_expf(__fsub_rn(x[3], mx)), __nv_expf(__fsub_rn(x[11], mx)));
        float t4 = __fadd_rn(__nv_expf(__fsub_rn(x[4], mx)), __nv_expf(__fsub_rn(x[12], mx)));
        float u0 = __fadd_rn(t0, t4);
        float u1 = __fadd_rn(t1, __nv_expf(__fsub_rn(x[5], mx)));
        float u2 = __fadd_rn(t2, __nv_expf(__fsub_rn(x[6], mx)));
        float u3 = __fadd_rn(t3, __nv_expf(__fsub_rn(x[7], mx)));
        float sm = __fadd_rn(__fadd_rn(u0, u2), __fadd_rn(u1, u3));
        float lse = __nv_logf(sm);
        s_pc[w][pair * 5 + track] = (unsigned char)am;
        float vals[5];
#pragma unroll
        for (int k = 0; k < 5; k++) {
            int idx = (k < v) ? (int)s_cls[w][k * 6 + pair] : 0;
            float xv = s_pred[w][idx * 30 + base];   // lse-(x[idx]-mx), same bits
            vals[k] = (k < v) ? __fsub_rn(lse, __fsub_rn(xv, mx)) : 0.0f;
        }
        __syncwarp(0x3fffffffu);   // s_tgt fully dead before lm overwrite
#pragma unroll
        for (int k = 0; k < 5; k++)
            s_lm[pair * 25 + k * 5 + track] = vals[k];
    }
    __syncwarp();

    // ---- perm argmin: group g (5 lanes) owns pair g ----
    // Slots k>=v contribute exact +0.0f to every perm, so all (5-v)! perms
    // sharing a v-prefix are bitwise-equal in cost; first occurrence is the
    // block start pe = q*(5-v)!. Enumerate only the nq = 120/(5-v)! starts.
    const int g   = (lane < 30) ? (lane / 5) : 6;
    const int lig = lane - g * 5;     // 0..4 within group (garbage for g==6)
    static __device__ const int FACT[6] = {120, 24, 6, 2, 1, 1};
    const int fac = FACT[v];
    const int nq  = (g < 6) ? (120 / fac) : 0;
    const float* lm = &s_lm[g * 25];  // g==6 -> out of 150 but never loaded (nq=0)

    // Two interleaved lazy-division chains for ILP; both exact first-occurrence.
    float bs0A = FLT_MAX, bcA = FLT_MAX;  int biA = 1 << 20;
    float bs0B = FLT_MAX, bcB = FLT_MAX;  int biB = 1 << 20;
#pragma unroll 1
    for (int q = lig; q < nq; q += 10) {
        {
            int pe = q * fac;
            unsigned ep = s_eperm[pe];
            float a0 = lm[ ep        & 31];
            float a1 = lm[(ep >> 5)  & 31];
            float a2 = lm[(ep >> 10) & 31];
            float a3 = lm[(ep >> 15) & 31];
            float a4 = lm[(ep >> 20) & 31];
            float s0 = __fadd_rn(__fadd_rn(__fadd_rn(a0, a4), a2),
                                 __fadd_rn(a1, a3));
            if (s0 < bs0A) {
                float cst = __fdiv_rn(s0, 5.0f);
                if (cst < bcA) { bcA = cst; biA = pe; }
                bs0A = s0;
            }
        }
        int q2 = q + 5;
        if (q2 < nq) {
            int pe = q2 * fac;
            unsigned ep = s_eperm[pe];
            float a0 = lm[ ep        & 31];
            float a1 = lm[(ep >> 5)  & 31];
            float a2 = lm[(ep >> 10) & 31];
            float a3 = lm[(ep >> 15) & 31];
            float a4 = lm[(ep >> 20) & 31];
            float s0 = __fadd_rn(__fadd_rn(__fadd_rn(a0, a4), a2),
                                 __fadd_rn(a1, a3));
            if (s0 < bs0B) {
                float cst = __fdiv_rn(s0, 5.0f);
                if (cst < bcB) { bcB = cst; biB = pe; }
                bs0B = s0;
            }
        }
    }
    // merge chains (chain indices disjoint; (val,idx) comparator exact)
    float bcst = bcA; int bidx = biA;
    if (bcB < bcst || (bcB == bcst && biB < bidx)) { bcst = bcB; bidx = biB; }

    // group reduce over 5 lanes (offsets 4,2,1, guarded)
#pragma unroll
    for (int off = 4; off; off >>= 1) {
        float ov = __shfl_down_sync(0xffffffffu, bcst, off);
        int   oi = __shfl_down_sync(0xffffffffu, bidx, off);
        if (lig + off < 5 && g < 6) {
            if (ov < bcst || (ov == bcst && oi < bidx)) { bcst = ov; bidx = oi; }
        }
    }

    // group leaders: accuracy count + stash results
    if (g < 6 && lig == 0) {
        unsigned pk = s_perm[bidx];
        int corr = 0;
#pragma unroll
        for (int i = 0; i < 5; i++) {
            int s = (pk >> (4 * i)) & 15;   // tgt_perm[i] = tgt[perm[i]]
            if (s < v && (int)s_pc[w][g * 5 + i] == (int)s_cls[w][s * 6 + g]) corr++;
        }
        s_gl[w][g] = bcst;
        s_gc[w][g] = corr;
    }
    __syncwarp();

    if (lane == 0) {
        double wl = 0.0;
        int    wc = 0;
#pragma unroll
        for (int gg = 0; gg < 6; gg++) {      // pair-ascending, same as before
            wl += (double)s_gl[w][gg];
            wc += s_gc[w][gg];
        }
        s_wl[w] = wl;
        s_wc[w] = wc;
        s_wn[w] = 6 * v;
    }
    __syncthreads();

    // ---- block accumulate -> buckets; last block finalizes output ----
    if (tid == 0) {
        double L = 0.0;
        int    C = 0, NP = 0;
#pragma unroll
        for (int i = 0; i < WPB; i++) { L += s_wl[i]; C += s_wc[i]; NP += s_wn[i]; }
        int bk = blockIdx.x & (NBUCK - 1);
        atomicAdd(&g_bl[bk], L);
        atomicAdd(&g_bc[bk], (unsigned long long)C);
        atomicAdd(&g_bn[bk], (unsigned long long)NP);
        __threadfence();
    }
    if (w == 0) {
        unsigned t = 0;
        if (lane == 0) t = atomicInc(&g_cnt, NBLK - 1);  // wraps -> clean state
        t = __shfl_sync(0xffffffffu, t, 0);
        if (t == NBLK - 1) {
            double             L = g_bl[lane];
            unsigned long long C = g_bc[lane];
            unsigned long long N = g_bn[lane];
            g_bl[lane] = 0.0;    // re-zero for next replay
            g_bc[lane] = 0ull;
            g_bn[lane] = 0ull;
#pragma unroll
            for (int off = 16; off; off >>= 1) {
                L += __shfl_down_sync(0xffffffffu, L, off);
                C += __shfl_down_sync(0xffffffffu, C, off);
                N += __shfl_down_sync(0xffffffffu, N, off);
            }
            if (lane == 0) {
                if (nout >= 1) out[0] = (float)(L / 192000.0);
                if (nout >= 2) out[1] = (N > 0) ? (float)((double)C / (double)N) : 0.0f;
            }
        }
    }
}

extern "C" void kernel_launch(void* const* d_in, const int* in_sizes, int n_in,
                              void* d_out, int out_size) {
    const float* pred   = (const float*)d_in[0];
    const float* target = (const float*)d_in[1];
    const float* mics   = (const float*)d_in[2];
    (void)in_sizes; (void)n_in;

    tdoa_main<<<NBLK, 256>>>(pred, target, mics, (float*)d_out, out_size);
}

// round 8
// speedup vs baseline: 1.3868x; 1.1229x over previous
#include <cuda_runtime.h>
#include <math.h>
#include <float.h>

// Accurate libdevice math (same routines XLA GPU lowers f32 exp/log to).
extern "C" __device__ float __nv_expf(float);
extern "C" __device__ float __nv_logf(float);

// B=64, T=500 -> 32000 (b,t) rows; NLOGIT=13, TR=5, P=6 pairs.
// pred  : (64,500,13,5,6) f32 -> 390 floats per (b,t)
// target: (64,500,5,5,13) f32 -> 325 floats per (b,t)
// mic_locs: (4,3) f32 ; out: [loss, acc] f32
//
// 256 threads = 8 warps, one (b,t) row per warp.
// Perm-argmin: 6 groups of 5 lanes; group g owns mic-pair g.

#define NBT    32000
#define WPB    8
#define NBLK   (NBT / WPB)   // 4000
#define NBUCK  32

__device__ double             g_bl[NBUCK];   // zero-init; last block re-zeroes
__device__ unsigned long long g_bc[NBUCK];
__device__ unsigned long long g_bn[NBUCK];
__device__ unsigned           g_cnt;         // wraps to 0 every full launch

// Lexicographic (itertools) permutation -> packed 5-bit fields (5k + digit_k).
__device__ __forceinline__ unsigned perm_pack5(int p) {
    int avail[5] = {0, 1, 2, 3, 4};
    const int fact[4] = {24, 6, 2, 1};
    unsigned ep = 0;
#pragma unroll
    for (int i = 0; i < 4; i++) {
        int d = p / fact[i];
        p -= d * fact[i];
        ep |= (unsigned)(5 * i + avail[d]) << (5 * i);
#pragma unroll
        for (int j = 0; j < 4; j++)
            if (j >= d) avail[j] = avail[j + 1];
    }
    ep |= (unsigned)(20 + avail[0]) << 20;
    return ep;
}

__global__ __launch_bounds__(256, 8) void tdoa_main(
    const float* __restrict__ pred,
    const float* __restrict__ target,
    const float* __restrict__ mics,
    float* __restrict__ out, int nout)
{
    __shared__ __align__(16) float s_pred[WPB][390];  // cl*30 + track*6 + pair
    // s_tgt (325 f) and s_lm (150 f) have disjoint lifetimes -> overlay.
    __shared__ __align__(16) float s_u[WPB][325];
    __shared__ unsigned char s_cls[WPB][32];   // slot*6 + pair
    __shared__ unsigned char s_pc[WPB][32];    // pair*5 + track
    __shared__ unsigned s_eperm[128];          // 5-bit (5k+digit); [120..]=0
    __shared__ float    s_mics[12];
    __shared__ float    s_gl[WPB][6];          // per-group best cost
    __shared__ int      s_gc[WPB][6];          // per-group correct count
    __shared__ double   s_wl[WPB];
    __shared__ int      s_wc[WPB], s_wn[WPB];

    const int tid  = threadIdx.x;
    const int w    = tid >> 5;
    const int lane = tid & 31;
    const int bt   = blockIdx.x * WPB + w;

    float* s_tgt = s_u[w];   // phase 1
    float* s_lm  = s_u[w];   // phase 2 (pair*25 + slot*5 + track)

    // ---- stage inputs + block tables ----
    {
        const float2* pb2 = (const float2*)(pred + (size_t)bt * 390u); // even -> 8B aligned
        float2* sp2 = (float2*)&s_pred[w][0];
#pragma unroll
        for (int i = 0; i < 6; i++) sp2[lane + 32 * i] = pb2[lane + 32 * i];
        if (lane < 3) sp2[192 + lane] = pb2[192 + lane];
        const float* tb = target + (size_t)bt * 325u;
        for (int i = lane; i < 325; i += 32) s_tgt[i] = tb[i];
    }
    if (tid < 128) s_eperm[tid] = (tid < 120) ? perm_pack5(tid) : 0u;
    if (tid < 12)  s_mics[tid] = mics[tid];
    __syncthreads();

    // ---- stable first-<=5 active selection via ballots (f = tr*13 + c) ----
    int f0 = lane, f1 = 32 + lane;
    int tr0 = f0 / 13, c0 = f0 - tr0 * 13;
    int tr1 = f1 / 13, c1 = f1 - tr1 * 13;
    unsigned b0 = __ballot_sync(0xffffffffu, s_tgt[tr0 * 65 + c0] != 0.0f);
    unsigned b1 = __ballot_sync(0xffffffffu, s_tgt[tr1 * 65 + c1] != 0.0f);
    int act64 = (s_tgt[4 * 65 + 12] != 0.0f) ? 1 : 0;   // f = 64
    unsigned long long bits = (unsigned long long)b0 |
                              ((unsigned long long)b1 << 32);
    int total = __popcll(bits) + act64;
    const int v = (total < 5) ? total : 5;

    // fsel on lanes 0..4 (others compute lane-0 copy), broadcast via shfl
    int fsel = 0;
    {
        int sl = (lane < 5) ? lane : 0;
        if (sl < v) {
            if (sl < __popcll(bits)) {
                unsigned long long t = bits;
#pragma unroll
                for (int j = 0; j < 4; j++)
                    if (j < sl) t &= t - 1;
                fsel = __ffsll((long long)t) - 1;
            } else {
                fsel = 64;
            }
        }
    }

    // ---- TDOA class per (slot, pair): 30 lanes ----
    {
        int s  = lane / 6;               // slot (lane<30)
        int pr = lane - s * 6;           // pair
        int f  = __shfl_sync(0xffffffffu, fsel, (s < 5) ? s : 0);
        if (lane < 30) {
            int cls = 0;
            if (s < v) {
                const int pa[6]  = {0, 0, 0, 1, 1, 2};
                const int pbx[6] = {1, 2, 3, 2, 3, 3};
                int tr = f / 13, c = f - tr * 13;
                float dist = s_tgt[tr * 65 + 52 + c];
                float sx = __fmul_rn(s_tgt[tr * 65 + 13 + c], dist);
                float sy = __fmul_rn(s_tgt[tr * 65 + 26 + c], dist);
                float sz = __fmul_rn(s_tgt[tr * 65 + 39 + c], dist);
                int ma = pa[pr], mb = pbx[pr];
                float dxa = __fsub_rn(sx, s_mics[ma * 3 + 0]);
                float dya = __fsub_rn(sy, s_mics[ma * 3 + 1]);
                float dza = __fsub_rn(sz, s_mics[ma * 3 + 2]);
                float dxb = __fsub_rn(sx, s_mics[mb * 3 + 0]);
                float dyb = __fsub_rn(sy, s_mics[mb * 3 + 1]);
                float dzb = __fsub_rn(sz, s_mics[mb * 3 + 2]);
                float qa = __fadd_rn(__fadd_rn(__fmul_rn(dxa, dxa), __fmul_rn(dya, dya)), __fmul_rn(dza, dza));
                float qb = __fadd_rn(__fadd_rn(__fmul_rn(dxb, dxb), __fmul_rn(dyb, dyb)), __fmul_rn(dzb, dzb));
                float tdoa = __fsub_rn(__fsqrt_rn(qa), __fsqrt_rn(qb));
                cls = (int)rintf(__fdiv_rn(__fmul_rn(tdoa, 24000.0f), 343.0f)) + 6;
            }
            s_cls[w][s * 6 + pr] = (unsigned char)cls;
        }
    }
    __syncwarp();

    // ---- log-softmax per (pair, track): 30 lanes, register-lean ----
    if (lane < 30) {
        const int pair  = lane / 5;
        const int track = lane - pair * 5;
        const float* xp = &s_pred[w][track * 6 + pair];   // stride 30

        // pass 1: max + first-occurrence argmax
        float mx = -FLT_MAX;
        int   am = 0;
#pragma unroll
        for (int cl = 0; cl < 13; cl++) {
            float x = xp[cl * 30];
            if (x > mx) { mx = x; am = cl; }
        }
        // pass 2: exp tree (XLA GPU 32-lane column reduction, leaves 13..31==0)
        float t0 = __fadd_rn(__nv_expf(__fsub_rn(xp[0],      mx)), __nv_expf(__fsub_rn(xp[8 * 30],  mx)));
        float t1 = __fadd_rn(__nv_expf(__fsub_rn(xp[1 * 30], mx)), __nv_expf(__fsub_rn(xp[9 * 30],  mx)));
        float t2 = __fadd_rn(__nv_expf(__fsub_rn(xp[2 * 30], mx)), __nv_expf(__fsub_rn(xp[10 * 30], mx)));
        float t3 = __fadd_rn(__nv_expf(__fsub_rn(xp[3 * 30], mx)), __nv_expf(__fsub_rn(xp[11 * 30], mx)));
        float t4 = __fadd_rn(__nv_expf(__fsub_rn(xp[4 * 30], mx)), __nv_expf(__fsub_rn(xp[12 * 30], mx)));
        float u0 = __fadd_rn(t0, t4);
        float u1 = __fadd_rn(t1, __nv_expf(__fsub_rn(xp[5 * 30], mx)));
        float u2 = __fadd_rn(t2, __nv_expf(__fsub_rn(xp[6 * 30], mx)));
        float u3 = __fadd_rn(t3, __nv_expf(__fsub_rn(xp[7 * 30], mx)));
        float sm = __fadd_rn(__fadd_rn(u0, u2), __fadd_rn(u1, u3));
        float lse = __nv_logf(sm);
        s_pc[w][pair * 5 + track] = (unsigned char)am;
        // pass 3: vals (re-read s_pred; lse-(x[idx]-mx) is bitwise lse-shifted)
        float vals[5];
#pragma unroll
        for (int k = 0; k < 5; k++) {
            int idx = (k < v) ? (int)s_cls[w][k * 6 + pair] : 0;
            float xv = xp[idx * 30];
            vals[k] = (k < v) ? __fsub_rn(lse, __fsub_rn(xv, mx)) : 0.0f;
        }
        __syncwarp(0x3fffffffu);   // s_tgt fully dead before lm overwrite
#pragma unroll
        for (int k = 0; k < 5; k++)
            s_lm[pair * 25 + k * 5 + track] = vals[k];
    }
    __syncwarp();

    // ---- perm argmin: group g (5 lanes) owns pair g ----
    // Slots k>=v contribute exact +0.0f, so perms sharing a v-prefix are
    // bitwise-equal; first occurrence is block start pe = q*(5-v)!.
    const int g   = (lane < 30) ? (lane / 5) : 6;
    const int lig = lane - g * 5;     // 0..4 in group
    static __device__ const int FACT[6] = {120, 24, 6, 2, 1, 1};
    const int fac = FACT[v];
    const int nq  = (g < 6) ? (120 / fac) : 0;
    const float* lm = &s_lm[g * 25];

    // Two interleaved lazy-division chains (cost = s0/5 monotone in s0;
    // divided-tie keeps earlier index -> exact first-occurrence argmin).
    float bs0A = FLT_MAX, bcA = FLT_MAX;  int biA = 1 << 20;
    float bs0B = FLT_MAX, bcB = FLT_MAX;  int biB = 1 << 20;
#pragma unroll 1
    for (int q = lig; q < nq; q += 10) {
        {
            int pe = q * fac;
            unsigned ep = s_eperm[pe];
            float a0 = lm[ ep        & 31];
            float a1 = lm[(ep >> 5)  & 31];
            float a2 = lm[(ep >> 10) & 31];
            float a3 = lm[(ep >> 15) & 31];
            float a4 = lm[(ep >> 20) & 31];
            float s0 = __fadd_rn(__fadd_rn(__fadd_rn(a0, a4), a2),
                                 __fadd_rn(a1, a3));
            if (s0 < bs0A) {
                float cst = __fdiv_rn(s0, 5.0f);
                if (cst < bcA) { bcA = cst; biA = pe; }
                bs0A = s0;
            }
        }
        int q2 = q + 5;
        if (q2 < nq) {
            int pe = q2 * fac;
            unsigned ep = s_eperm[pe];
            float a0 = lm[ ep        & 31];
            float a1 = lm[(ep >> 5)  & 31];
            float a2 = lm[(ep >> 10) & 31];
            float a3 = lm[(ep >> 15) & 31];
            float a4 = lm[(ep >> 20) & 31];
            float s0 = __fadd_rn(__fadd_rn(__fadd_rn(a0, a4), a2),
                                 __fadd_rn(a1, a3));
            if (s0 < bs0B) {
                float cst = __fdiv_rn(s0, 5.0f);
                if (cst < bcB) { bcB = cst; biB = pe; }
                bs0B = s0;
            }
        }
    }
    float bcst = bcA; int bidx = biA;
    if (bcB < bcst || (bcB == bcst && biB < bidx)) { bcst = bcB; bidx = biB; }

    // group reduce over 5 lanes (offsets 4,2,1, guarded)
#pragma unroll
    for (int off = 4; off; off >>= 1) {
        float ov = __shfl_down_sync(0xffffffffu, bcst, off);
        int   oi = __shfl_down_sync(0xffffffffu, bidx, off);
        if (lig + off < 5 && g < 6) {
            if (ov < bcst || (ov == bcst && oi < bidx)) { bcst = ov; bidx = oi; }
        }
    }

    // group leaders: accuracy count + stash results
    if (g < 6 && lig == 0) {
        unsigned ep = s_eperm[bidx];
        int corr = 0;
#pragma unroll
        for (int i = 0; i < 5; i++) {
            int s = (int)((ep >> (5 * i)) & 31) - 5 * i;  // tgt_perm[i]
            if (s < v && (int)s_pc[w][g * 5 + i] == (int)s_cls[w][s * 6 + g]) corr++;
        }
        s_gl[w][g] = bcst;
        s_gc[w][g] = corr;
    }
    __syncwarp();

    if (lane == 0) {
        double wl = 0.0;
        int    wc = 0;
#pragma unroll
        for (int gg = 0; gg < 6; gg++) {
            wl += (double)s_gl[w][gg];
            wc += s_gc[w][gg];
        }
        s_wl[w] = wl;
        s_wc[w] = wc;
        s_wn[w] = 6 * v;
    }
    __syncthreads();

    // ---- block accumulate -> buckets; last block finalizes output ----
    if (tid == 0) {
        double L = 0.0;
        int    C = 0, NP = 0;
#pragma unroll
        for (int i = 0; i < WPB; i++) { L += s_wl[i]; C += s_wc[i]; NP += s_wn[i]; }
        int bk = blockIdx.x & (NBUCK - 1);
        atomicAdd(&g_bl[bk], L);
        atomicAdd(&g_bc[bk], (unsigned long long)C);
        atomicAdd(&g_bn[bk], (unsigned long long)NP);
        __threadfence();
    }
    if (w == 0) {
        unsigned t = 0;
        if (lane == 0) t = atomicInc(&g_cnt, NBLK - 1);  // wraps -> clean state
        t = __shfl_sync(0xffffffffu, t, 0);
        if (t == NBLK - 1) {
            double             L = g_bl[lane];
            unsigned long long C = g_bc[lane];
            unsigned long long N = g_bn[lane];
            g_bl[lane] = 0.0;    // re-zero for next replay
            g_bc[lane] = 0ull;
            g_bn[lane] = 0ull;
#pragma unroll
            for (int off = 16; off; off >>= 1) {
                L += __shfl_down_sync(0xffffffffu, L, off);
                C += __shfl_down_sync(0xffffffffu, C, off);
                N += __shfl_down_sync(0xffffffffu, N, off);
            }
            if (lane == 0) {
                if (nout >= 1) out[0] = (float)(L / 192000.0);
                if (nout >= 2) out[1] = (N > 0) ? (float)((double)C / (double)N) : 0.0f;
            }
        }
    }
}

extern "C" void kernel_launch(void* const* d_in, const int* in_sizes, int n_in,
                              void* d_out, int out_size) {
    const float* pred   = (const float*)d_in[0];
    const float* target = (const float*)d_in[1];
    const float* mics   = (const float*)d_in[2];
    (void)in_sizes; (void)n_in;

    tdoa_main<<<NBLK, 256>>>(pred, target, mics, (float*)d_out, out_size);
}